// round 4
// baseline (speedup 1.0000x reference)
#include <cuda_runtime.h>
#include <math.h>

#define NN 100000
#define NE 1600000
#define DD 128
#define KK 256      // concat(mean, x) inner dim
#define BM 128
#define BK 8
#define NB 391      // ceil(NN/256) blocks for the scan

// Scratch (device globals — no allocation allowed)
__device__ float g_agg[(size_t)NN * DD];   // mean-aggregated features, 51.2 MB
__device__ float g_rcp[NN];
__device__ float g_sl[NN];
__device__ float g_pre[NN];
__device__ float g_wt[KK * DD];            // transposed [k][n] weights
__device__ int   g_cnt[NN];
__device__ int   g_off[NN];
__device__ int   g_cur[NN];
__device__ int   g_esrc[NE];               // CSR: src indices sorted by dst
__device__ int   g_partial[512];
__device__ int   g_pinc[512];
__device__ int   g_is64;

// ---- packed fp32 helpers ----------------------------------------------------
__device__ __forceinline__ unsigned long long pack2(float x, float y) {
    unsigned long long r;
    asm("mov.b64 %0, {%1, %2};" : "=l"(r) : "f"(x), "f"(y));
    return r;
}
__device__ __forceinline__ void fma2(unsigned long long& d,
                                     unsigned long long a,
                                     unsigned long long b) {
    asm("fma.rn.f32x2 %0, %1, %2, %0;" : "+l"(d) : "l"(a), "l"(b));
}
__device__ __forceinline__ void unpack2(unsigned long long v, float& lo, float& hi) {
    asm("mov.b64 {%0, %1}, %2;" : "=f"(lo), "=f"(hi) : "l"(v));
}

// ---------------------------------------------------------------------------
// Detect edge_index dtype (int32 vs int64): for int64 < 2^31 every odd 32-bit
// word is 0; 16 consecutive zeros in random int32 data has prob ~1e-80.
__global__ void detect_kernel(const int* __restrict__ e) {
    if (threadIdx.x == 0) {
        int z = 0;
#pragma unroll
        for (int i = 1; i < 32; i += 2) z |= e[i];
        g_is64 = (z == 0) ? 1 : 0;
    }
}

__global__ void zero_cnt_kernel() {
    int i = blockIdx.x * 256 + threadIdx.x;
    if (i < NN) g_cnt[i] = 0;
}

// Histogram of dst degrees.
__global__ void hist_kernel(const int* __restrict__ e32,
                            const long long* __restrict__ e64) {
    unsigned e = blockIdx.x * 256u + threadIdx.x;
    if (e >= NE) return;
    int dst = g_is64 ? (int)__ldg(&e64[NE + e]) : __ldg(&e32[NE + e]);
    atomicAdd(&g_cnt[dst], 1);
}

// Per-256-block sums of g_cnt.
__global__ void block_sum_kernel() {
    __shared__ int s[256];
    int b = blockIdx.x, t = threadIdx.x;
    int i = b * 256 + t;
    s[t] = (i < NN) ? g_cnt[i] : 0;
    __syncthreads();
#pragma unroll
    for (int off = 128; off > 0; off >>= 1) {
        if (t < off) s[t] += s[t + off];
        __syncthreads();
    }
    if (t == 0) g_partial[b] = s[0];
}

// Inclusive scan of the NB partials (one block).
__global__ void scan_partial_kernel() {
    __shared__ int s[512];
    int t = threadIdx.x;
    s[t] = (t < NB) ? g_partial[t] : 0;
    __syncthreads();
#pragma unroll
    for (int off = 1; off < 512; off <<= 1) {
        int v = (t >= off) ? s[t - off] : 0;
        __syncthreads();
        s[t] += v;
        __syncthreads();
    }
    if (t < NB) g_pinc[t] = s[t];
}

// Per-block inclusive scan + base -> exclusive offsets; also rcp and cursor.
__global__ void block_scan_kernel() {
    __shared__ int s[256];
    int b = blockIdx.x, t = threadIdx.x;
    int i = b * 256 + t;
    int c = (i < NN) ? g_cnt[i] : 0;
    s[t] = c;
    __syncthreads();
#pragma unroll
    for (int off = 1; off < 256; off <<= 1) {
        int v = (t >= off) ? s[t - off] : 0;
        __syncthreads();
        s[t] += v;
        __syncthreads();
    }
    if (i < NN) {
        int base = (b > 0) ? g_pinc[b - 1] : 0;
        int excl = base + s[t] - c;
        g_off[i] = excl;
        g_cur[i] = excl;
        g_rcp[i] = 1.f / fmaxf((float)c, 1.f);
    }
}

// Scatter src into CSR order.
__global__ void scatter_kernel(const int* __restrict__ e32,
                               const long long* __restrict__ e64) {
    unsigned e = blockIdx.x * 256u + threadIdx.x;
    if (e >= NE) return;
    int src, dst;
    if (g_is64) {
        src = (int)__ldg(&e64[e]);
        dst = (int)__ldg(&e64[NE + e]);
    } else {
        src = __ldg(&e32[e]);
        dst = __ldg(&e32[NE + e]);
    }
    int pos = atomicAdd(&g_cur[dst], 1);
    g_esrc[pos] = src;
}

// Transpose+concat weights: g_wt[k][n] = (k<128 ? w1l[n][k] : w1r[n][k-128])
__global__ void trans_kernel(const float* __restrict__ w1l,
                             const float* __restrict__ w1r) {
    int idx = blockIdx.x * 256 + threadIdx.x;      // 0 .. 32767
    if (idx < KK * DD) {
        int k = idx >> 7, n = idx & 127;
        g_wt[idx] = (k < DD) ? w1l[n * DD + k] : w1r[n * DD + (k - DD)];
    }
}

// ---------------------------------------------------------------------------
// Gather-style mean aggregation: one warp per node, neighbors from CSR.
__global__ void __launch_bounds__(256) agg_kernel(const float* __restrict__ x) {
    unsigned tid  = blockIdx.x * 256u + threadIdx.x;
    unsigned row  = tid >> 5;
    if (row >= NN) return;
    unsigned lane = tid & 31;
    int beg = g_off[row];
    int end = beg + g_cnt[row];
    float4 a0 = make_float4(0.f, 0.f, 0.f, 0.f);
    float4 a1 = make_float4(0.f, 0.f, 0.f, 0.f);
    int e = beg;
    for (; e + 1 < end; e += 2) {
        int s0 = __ldg(&g_esrc[e]);
        int s1 = __ldg(&g_esrc[e + 1]);
        float4 v0 = __ldg((const float4*)(x + (size_t)s0 * DD) + lane);
        float4 v1 = __ldg((const float4*)(x + (size_t)s1 * DD) + lane);
        a0.x += v0.x; a0.y += v0.y; a0.z += v0.z; a0.w += v0.w;
        a1.x += v1.x; a1.y += v1.y; a1.z += v1.z; a1.w += v1.w;
    }
    if (e < end) {
        int s0 = __ldg(&g_esrc[e]);
        float4 v0 = __ldg((const float4*)(x + (size_t)s0 * DD) + lane);
        a0.x += v0.x; a0.y += v0.y; a0.z += v0.z; a0.w += v0.w;
    }
    float r = g_rcp[row];
    float4 m = make_float4((a0.x + a1.x) * r, (a0.y + a1.y) * r,
                           (a0.z + a1.z) * r, (a0.w + a1.w) * r);
    *((float4*)(g_agg + (size_t)row * DD) + lane) = m;
}

// ---------------------------------------------------------------------------
// Layer-1 GEMM: h = [mean | x] (100k x 256) @ g_wt (256 x 128) + b1.
// Double-buffered SGEMM with packed fma.rn.f32x2: 8x8 tile = 8x4 f32x2 accs.
__global__ void __launch_bounds__(256, 2) sage1_kernel(
    const float* __restrict__ x, const float* __restrict__ b1l,
    float* __restrict__ outh) {
    __shared__ float As[2][BK][BM];
    __shared__ float Bs[2][BK][DD];

    const int tid = threadIdx.x;
    const int m0  = blockIdx.x * BM;
    const int tx  = tid & 15, ty = tid >> 4;

    const int arow = tid >> 1;
    const int akq  = (tid & 1) * 4;
    const int am   = m0 + arow;
    const bool avalid = (am < NN);
    const int bkr = tid >> 5;
    const int bc  = (tid & 31) * 4;

    unsigned long long acc[8][4];
#pragma unroll
    for (int i = 0; i < 8; i++)
#pragma unroll
        for (int j = 0; j < 4; j++) acc[i][j] = 0ull;

    auto fetchA = [&](int k0) -> float4 {
        float4 v = make_float4(0.f, 0.f, 0.f, 0.f);
        if (avalid) {
            int k = k0 + akq;
            if (k < DD)
                v = *(const float4*)(g_agg + (size_t)am * DD + k);
            else
                v = __ldg((const float4*)(x + (size_t)am * DD + (k - DD)));
        }
        return v;
    };
    auto fetchB = [&](int k0) -> float4 {
        return *(const float4*)(g_wt + (k0 + bkr) * DD + bc);
    };

    {
        float4 pa = fetchA(0), pb = fetchB(0);
        As[0][akq + 0][arow] = pa.x;
        As[0][akq + 1][arow] = pa.y;
        As[0][akq + 2][arow] = pa.z;
        As[0][akq + 3][arow] = pa.w;
        *(float4*)&Bs[0][bkr][bc] = pb;
    }
    __syncthreads();

    int s = 0;
    for (int k0 = 0; k0 < KK; k0 += BK) {
        float4 pa, pb;
        const bool more = (k0 + BK < KK);
        if (more) { pa = fetchA(k0 + BK); pb = fetchB(k0 + BK); }

#pragma unroll
        for (int kk = 0; kk < BK; kk++) {
            float4 a0 = *(const float4*)&As[s][kk][ty * 8];
            float4 a1 = *(const float4*)&As[s][kk][ty * 8 + 4];
            float4 b0 = *(const float4*)&Bs[s][kk][tx * 8];
            float4 b1 = *(const float4*)&Bs[s][kk][tx * 8 + 4];
            unsigned long long bv[4];
            bv[0] = pack2(b0.x, b0.y);
            bv[1] = pack2(b0.z, b0.w);
            bv[2] = pack2(b1.x, b1.y);
            bv[3] = pack2(b1.z, b1.w);
            unsigned long long av[8];
            av[0] = pack2(a0.x, a0.x); av[1] = pack2(a0.y, a0.y);
            av[2] = pack2(a0.z, a0.z); av[3] = pack2(a0.w, a0.w);
            av[4] = pack2(a1.x, a1.x); av[5] = pack2(a1.y, a1.y);
            av[6] = pack2(a1.z, a1.z); av[7] = pack2(a1.w, a1.w);
#pragma unroll
            for (int i = 0; i < 8; i++)
#pragma unroll
                for (int j = 0; j < 4; j++)
                    fma2(acc[i][j], av[i], bv[j]);
        }

        if (more) {
            int ns = s ^ 1;
            As[ns][akq + 0][arow] = pa.x;
            As[ns][akq + 1][arow] = pa.y;
            As[ns][akq + 2][arow] = pa.z;
            As[ns][akq + 3][arow] = pa.w;
            *(float4*)&Bs[ns][bkr][bc] = pb;
            __syncthreads();
            s = ns;
        }
    }

    float4 bb0 = __ldg((const float4*)b1l + tx * 2);
    float4 bb1 = __ldg((const float4*)b1l + tx * 2 + 1);
#pragma unroll
    for (int i = 0; i < 8; i++) {
        int m = m0 + ty * 8 + i;
        if (m < NN) {
            float c0, c1, c2, c3, c4, c5, c6, c7;
            unpack2(acc[i][0], c0, c1);
            unpack2(acc[i][1], c2, c3);
            unpack2(acc[i][2], c4, c5);
            unpack2(acc[i][3], c6, c7);
            float4 o0 = make_float4(c0 + bb0.x, c1 + bb0.y,
                                    c2 + bb0.z, c3 + bb0.w);
            float4 o1 = make_float4(c4 + bb1.x, c5 + bb1.y,
                                    c6 + bb1.z, c7 + bb1.w);
            float* op = outh + (size_t)m * DD + tx * 8;
            *(float4*)op       = o0;
            *(float4*)(op + 4) = o1;
        }
    }
}

// ---------------------------------------------------------------------------
// Layer-2 projection: one warp per row.
__global__ void __launch_bounds__(256) proj_kernel(
    const float* __restrict__ outh,
    const float* __restrict__ w2l, const float* __restrict__ b2l,
    const float* __restrict__ w2r) {
    unsigned tid  = blockIdx.x * 256u + threadIdx.x;
    unsigned row  = tid >> 5;
    if (row >= NN) return;
    unsigned lane = tid & 31;
    float4 h  = __ldg((const float4*)(outh + (size_t)row * DD) + lane);
    float4 wl = __ldg((const float4*)w2l + lane);
    float4 wr = __ldg((const float4*)w2r + lane);
    float r0 = fmaxf(h.x, 0.f), r1 = fmaxf(h.y, 0.f);
    float r2 = fmaxf(h.z, 0.f), r3 = fmaxf(h.w, 0.f);
    float sl = r0 * wl.x + r1 * wl.y + r2 * wl.z + r3 * wl.w;
    float sr = r0 * wr.x + r1 * wr.y + r2 * wr.z + r3 * wr.w;
#pragma unroll
    for (int off = 16; off > 0; off >>= 1) {
        sl += __shfl_xor_sync(0xffffffffu, sl, off);
        sr += __shfl_xor_sync(0xffffffffu, sr, off);
    }
    if (lane == 0) { g_sl[row] = sl; g_pre[row] = sr + __ldg(b2l); }
}

// ---------------------------------------------------------------------------
// Layer-2 aggregation (CSR gather) + sigmoid, fused. Thread per node.
__global__ void final_kernel(float* __restrict__ out0) {
    int i = blockIdx.x * 256 + threadIdx.x;
    if (i >= NN) return;
    int beg = g_off[i];
    int end = beg + g_cnt[i];
    float t = 0.f;
    for (int e = beg; e < end; e++) t += __ldg(&g_sl[__ldg(&g_esrc[e])]);
    float v = t * g_rcp[i] + g_pre[i];
    out0[i] = 1.f / (1.f + expf(-v));
}

// ---------------------------------------------------------------------------
extern "C" void kernel_launch(void* const* d_in, const int* in_sizes, int n_in,
                              void* d_out, int out_size) {
    const float*     x   = (const float*)d_in[0];
    const int*       e32 = (const int*)d_in[1];
    const long long* e64 = (const long long*)d_in[1];
    const float*     w1l = (const float*)d_in[2];
    const float*     b1l = (const float*)d_in[3];
    const float*     w1r = (const float*)d_in[4];
    const float*     w2l = (const float*)d_in[5];
    const float*     b2l = (const float*)d_in[6];
    const float*     w2r = (const float*)d_in[7];
    float* out0 = (float*)d_out;       // out [N,1]
    float* outh = out0 + NN;           // h   [N,128]

    detect_kernel<<<1, 32>>>(e32);
    zero_cnt_kernel<<<NB, 256>>>();
    hist_kernel<<<(NE + 255) / 256, 256>>>(e32, e64);
    block_sum_kernel<<<NB, 256>>>();
    scan_partial_kernel<<<1, 512>>>();
    block_scan_kernel<<<NB, 256>>>();
    scatter_kernel<<<(NE + 255) / 256, 256>>>(e32, e64);
    trans_kernel<<<(KK * DD) / 256, 256>>>(w1l, w1r);
    agg_kernel<<<(NN * 32 + 255) / 256, 256>>>(x);
    sage1_kernel<<<(NN + BM - 1) / BM, 256>>>(x, b1l, outh);
    proj_kernel<<<(NN * 32 + 255) / 256, 256>>>(outh, w2l, b2l, w2r);
    final_kernel<<<(NN + 255) / 256, 256>>>(out0);
}

// round 6
// speedup vs baseline: 1.3356x; 1.3356x over previous
#include <cuda_runtime.h>
#include <cuda_bf16.h>
#include <math.h>
#include <stdint.h>

#define NN 100000
#define NE 1600000
#define DD 128
#define NB 391            // ceil(NN/256)
#define BMT 128           // GEMM M tile per CTA

// Scratch (device globals — no allocation allowed)
__device__ float g_agg[(size_t)NN * DD];
__device__ float g_rcp[NN];
__device__ float g_sl[NN];
__device__ float g_pre[NN];
__device__ uint32_t g_bfh[16 * 16 * 2 * 32];   // B hi frags, [ks][ntg][reg][lane]
__device__ uint32_t g_bfl[16 * 16 * 2 * 32];   // B lo frags
__device__ int   g_cnt[NN];
__device__ int   g_off[NN];
__device__ int   g_cur[NN];
__device__ int   g_esrc[NE];
__device__ int   g_partial[512];
__device__ int   g_pinc[512];
__device__ int   g_is64;

// ---- bf16 helpers -----------------------------------------------------------
__device__ __forceinline__ uint32_t bfpack(float a, float b) {
    __nv_bfloat162 t = __floats2bfloat162_rn(a, b);   // .x = a (low 16 bits)
    return *reinterpret_cast<uint32_t*>(&t);
}
__device__ __forceinline__ float bfres(float v) {
    return v - __bfloat162float(__float2bfloat16_rn(v));
}
#define MMA_BF16(d, a0, a1, a2, a3, b0, b1)                                    \
    asm volatile(                                                              \
        "mma.sync.aligned.m16n8k16.row.col.f32.bf16.bf16.f32 "                 \
        "{%0,%1,%2,%3}, {%4,%5,%6,%7}, {%8,%9}, {%0,%1,%2,%3};"                \
        : "+f"(d[0]), "+f"(d[1]), "+f"(d[2]), "+f"(d[3])                       \
        : "r"(a0), "r"(a1), "r"(a2), "r"(a3), "r"(b0), "r"(b1))

// ---------------------------------------------------------------------------
// Detect edge_index dtype (int32 vs int64).
__global__ void detect_kernel(const int* __restrict__ e) {
    if (threadIdx.x == 0) {
        int z = 0;
#pragma unroll
        for (int i = 1; i < 32; i += 2) z |= e[i];
        g_is64 = (z == 0) ? 1 : 0;
    }
}

__global__ void zero_cnt_kernel() {
    int i = blockIdx.x * 256 + threadIdx.x;
    if (i < NN) g_cnt[i] = 0;
}

__global__ void hist_kernel(const int* __restrict__ e32,
                            const long long* __restrict__ e64) {
    unsigned e = blockIdx.x * 256u + threadIdx.x;
    if (e >= NE) return;
    int dst = g_is64 ? (int)__ldg(&e64[NE + e]) : __ldg(&e32[NE + e]);
    atomicAdd(&g_cnt[dst], 1);
}

__global__ void block_sum_kernel() {
    __shared__ int s[256];
    int b = blockIdx.x, t = threadIdx.x;
    int i = b * 256 + t;
    s[t] = (i < NN) ? g_cnt[i] : 0;
    __syncthreads();
#pragma unroll
    for (int off = 128; off > 0; off >>= 1) {
        if (t < off) s[t] += s[t + off];
        __syncthreads();
    }
    if (t == 0) g_partial[b] = s[0];
}

__global__ void scan_partial_kernel() {
    __shared__ int s[512];
    int t = threadIdx.x;
    s[t] = (t < NB) ? g_partial[t] : 0;
    __syncthreads();
#pragma unroll
    for (int off = 1; off < 512; off <<= 1) {
        int v = (t >= off) ? s[t - off] : 0;
        __syncthreads();
        s[t] += v;
        __syncthreads();
    }
    if (t < NB) g_pinc[t] = s[t];
}

__global__ void block_scan_kernel() {
    __shared__ int s[256];
    int b = blockIdx.x, t = threadIdx.x;
    int i = b * 256 + t;
    int c = (i < NN) ? g_cnt[i] : 0;
    s[t] = c;
    __syncthreads();
#pragma unroll
    for (int off = 1; off < 256; off <<= 1) {
        int v = (t >= off) ? s[t - off] : 0;
        __syncthreads();
        s[t] += v;
        __syncthreads();
    }
    if (i < NN) {
        int base = (b > 0) ? g_pinc[b - 1] : 0;
        int excl = base + s[t] - c;
        g_off[i] = excl;
        g_cur[i] = excl;
        g_rcp[i] = 1.f / fmaxf((float)c, 1.f);
    }
}

__global__ void scatter_kernel(const int* __restrict__ e32,
                               const long long* __restrict__ e64) {
    unsigned e = blockIdx.x * 256u + threadIdx.x;
    if (e >= NE) return;
    int src, dst;
    if (g_is64) {
        src = (int)__ldg(&e64[e]);
        dst = (int)__ldg(&e64[NE + e]);
    } else {
        src = __ldg(&e32[e]);
        dst = __ldg(&e32[NE + e]);
    }
    int pos = atomicAdd(&g_cur[dst], 1);
    g_esrc[pos] = src;
}

// B prep: pack concat(w1l,w1r) into per-thread mma fragment order, bf16 hi/lo.
// Fragment F(ks, ntg, r, lane): elements B[k][n], k = ks*16 + r*8 + (lane&3)*2
// (+1), n = ntg*8 + (lane>>2), where B[k][n] = k<128 ? w1l[n][k] : w1r[n][k-128].
__global__ void prep_bfrag_kernel(const float* __restrict__ w1l,
                                  const float* __restrict__ w1r) {
    int idx = blockIdx.x * 256 + threadIdx.x;      // 0 .. 16383
    if (idx >= 16 * 16 * 2 * 32) return;
    int lane = idx & 31;
    int r    = (idx >> 5) & 1;
    int ntg  = (idx >> 6) & 15;
    int ks   = idx >> 10;
    int k    = ks * 16 + r * 8 + (lane & 3) * 2;
    int n    = ntg * 8 + (lane >> 2);
    float v0 = (k < DD)     ? w1l[n * DD + k]       : w1r[n * DD + k - DD];
    float v1 = (k + 1 < DD) ? w1l[n * DD + k + 1]   : w1r[n * DD + k + 1 - DD];
    g_bfh[idx] = bfpack(v0, v1);
    g_bfl[idx] = bfpack(bfres(v0), bfres(v1));
}

// ---------------------------------------------------------------------------
// Gather-style mean aggregation: one warp per node, neighbors from CSR.
__global__ void __launch_bounds__(256) agg_kernel(const float* __restrict__ x) {
    unsigned tid  = blockIdx.x * 256u + threadIdx.x;
    unsigned row  = tid >> 5;
    if (row >= NN) return;
    unsigned lane = tid & 31;
    int beg = g_off[row];
    int end = beg + g_cnt[row];
    float4 a0 = make_float4(0.f, 0.f, 0.f, 0.f);
    float4 a1 = make_float4(0.f, 0.f, 0.f, 0.f);
    int e = beg;
    for (; e + 1 < end; e += 2) {
        int s0 = __ldg(&g_esrc[e]);
        int s1 = __ldg(&g_esrc[e + 1]);
        float4 v0 = __ldg((const float4*)(x + (size_t)s0 * DD) + lane);
        float4 v1 = __ldg((const float4*)(x + (size_t)s1 * DD) + lane);
        a0.x += v0.x; a0.y += v0.y; a0.z += v0.z; a0.w += v0.w;
        a1.x += v1.x; a1.y += v1.y; a1.z += v1.z; a1.w += v1.w;
    }
    if (e < end) {
        int s0 = __ldg(&g_esrc[e]);
        float4 v0 = __ldg((const float4*)(x + (size_t)s0 * DD) + lane);
        a0.x += v0.x; a0.y += v0.y; a0.z += v0.z; a0.w += v0.w;
    }
    float r = g_rcp[row];
    float4 m = make_float4((a0.x + a1.x) * r, (a0.y + a1.y) * r,
                           (a0.z + a1.z) * r, (a0.w + a1.w) * r);
    *((float4*)(g_agg + (size_t)row * DD) + lane) = m;
}

// ---------------------------------------------------------------------------
// Layer-1 GEMM on tensor cores via mma.sync bf16 with 3-term hi/lo split.
// CTA: 128 rows x 128 cols. 8 warps in 4(M) x 2(N); warp = 32 rows x 64 cols.
// A fragments loaded directly from global fp32 (float2 per reg pair) and split
// to bf16 hi/lo in registers; B fragments pre-packed in g_bfh/g_bfl.
__global__ void __launch_bounds__(256) sage1_mma_kernel(
    const float* __restrict__ x, const float* __restrict__ b1l,
    float* __restrict__ outh) {
    const int tid  = threadIdx.x;
    const int w    = tid >> 5;
    const int lane = tid & 31;
    const int gid  = lane >> 2;
    const int tig  = lane & 3;
    const int m0   = blockIdx.x * BMT;

    const int mrow   = m0 + (w & 3) * 32;
    const int ncol   = (w >> 2) * 64;
    const int ntbase = (w >> 2) * 8;

    float acc[2][8][4];
#pragma unroll
    for (int mt = 0; mt < 2; mt++)
#pragma unroll
        for (int nt = 0; nt < 8; nt++)
#pragma unroll
            for (int q = 0; q < 4; q++) acc[mt][nt][q] = 0.f;

#pragma unroll 1
    for (int ks = 0; ks < 16; ks++) {
        // k<128 comes from g_agg (mean), k>=128 from x; ks<8 <=> k<128.
        const float* base = (ks < 8) ? (const float*)g_agg : (x - DD);
        const int kk = ks * 16 + tig * 2;

        uint32_t ah[2][4], al[2][4];
#pragma unroll
        for (int mt = 0; mt < 2; mt++) {
            int ra = mrow + mt * 16 + gid;
            int rb = ra + 8;
            bool va = ra < NN, vb = rb < NN;
            float2 z = make_float2(0.f, 0.f);
            float2 p0 = va ? *(const float2*)(base + (size_t)ra * DD + kk)     : z;
            float2 p1 = vb ? *(const float2*)(base + (size_t)rb * DD + kk)     : z;
            float2 p2 = va ? *(const float2*)(base + (size_t)ra * DD + kk + 8) : z;
            float2 p3 = vb ? *(const float2*)(base + (size_t)rb * DD + kk + 8) : z;
            ah[mt][0] = bfpack(p0.x, p0.y);
            ah[mt][1] = bfpack(p1.x, p1.y);
            ah[mt][2] = bfpack(p2.x, p2.y);
            ah[mt][3] = bfpack(p3.x, p3.y);
            al[mt][0] = bfpack(bfres(p0.x), bfres(p0.y));
            al[mt][1] = bfpack(bfres(p1.x), bfres(p1.y));
            al[mt][2] = bfpack(bfres(p2.x), bfres(p2.y));
            al[mt][3] = bfpack(bfres(p3.x), bfres(p3.y));
        }

#pragma unroll
        for (int nt = 0; nt < 8; nt++) {
            int fi = ((ks * 16 + ntbase + nt) * 2) * 32 + lane;
            uint32_t bh0 = __ldg(&g_bfh[fi]);
            uint32_t bh1 = __ldg(&g_bfh[fi + 32]);
            uint32_t bl0 = __ldg(&g_bfl[fi]);
            uint32_t bl1 = __ldg(&g_bfl[fi + 32]);
#pragma unroll
            for (int mt = 0; mt < 2; mt++) {
                MMA_BF16(acc[mt][nt], ah[mt][0], ah[mt][1], ah[mt][2], ah[mt][3],
                         bh0, bh1);
                MMA_BF16(acc[mt][nt], al[mt][0], al[mt][1], al[mt][2], al[mt][3],
                         bh0, bh1);
                MMA_BF16(acc[mt][nt], ah[mt][0], ah[mt][1], ah[mt][2], ah[mt][3],
                         bl0, bl1);
            }
        }
    }

    // Epilogue: + bias, store h (pre-relu). D frag: d0,d1 -> (gid, 2tig/+1);
    // d2,d3 -> (gid+8, 2tig/+1).
#pragma unroll
    for (int mt = 0; mt < 2; mt++) {
        int ra = mrow + mt * 16 + gid;
        int rb = ra + 8;
#pragma unroll
        for (int nt = 0; nt < 8; nt++) {
            int col = ncol + nt * 8 + tig * 2;
            float2 bias = *(const float2*)(b1l + col);
            if (ra < NN)
                *(float2*)(outh + (size_t)ra * DD + col) =
                    make_float2(acc[mt][nt][0] + bias.x, acc[mt][nt][1] + bias.y);
            if (rb < NN)
                *(float2*)(outh + (size_t)rb * DD + col) =
                    make_float2(acc[mt][nt][2] + bias.x, acc[mt][nt][3] + bias.y);
        }
    }
}

// ---------------------------------------------------------------------------
// Layer-2 projection: one warp per row.
__global__ void __launch_bounds__(256) proj_kernel(
    const float* __restrict__ outh,
    const float* __restrict__ w2l, const float* __restrict__ b2l,
    const float* __restrict__ w2r) {
    unsigned tid  = blockIdx.x * 256u + threadIdx.x;
    unsigned row  = tid >> 5;
    if (row >= NN) return;
    unsigned lane = tid & 31;
    float4 h  = __ldg((const float4*)(outh + (size_t)row * DD) + lane);
    float4 wl = __ldg((const float4*)w2l + lane);
    float4 wr = __ldg((const float4*)w2r + lane);
    float r0 = fmaxf(h.x, 0.f), r1 = fmaxf(h.y, 0.f);
    float r2 = fmaxf(h.z, 0.f), r3 = fmaxf(h.w, 0.f);
    float sl = r0 * wl.x + r1 * wl.y + r2 * wl.z + r3 * wl.w;
    float sr = r0 * wr.x + r1 * wr.y + r2 * wr.z + r3 * wr.w;
#pragma unroll
    for (int off = 16; off > 0; off >>= 1) {
        sl += __shfl_xor_sync(0xffffffffu, sl, off);
        sr += __shfl_xor_sync(0xffffffffu, sr, off);
    }
    if (lane == 0) { g_sl[row] = sl; g_pre[row] = sr + __ldg(b2l); }
}

// Layer-2 aggregation (CSR gather) + sigmoid, fused.
__global__ void final_kernel(float* __restrict__ out0) {
    int i = blockIdx.x * 256 + threadIdx.x;
    if (i >= NN) return;
    int beg = g_off[i];
    int end = beg + g_cnt[i];
    float t = 0.f;
    for (int e = beg; e < end; e++) t += __ldg(&g_sl[__ldg(&g_esrc[e])]);
    float v = t * g_rcp[i] + g_pre[i];
    out0[i] = 1.f / (1.f + expf(-v));
}

// ---------------------------------------------------------------------------
extern "C" void kernel_launch(void* const* d_in, const int* in_sizes, int n_in,
                              void* d_out, int out_size) {
    const float*     x   = (const float*)d_in[0];
    const int*       e32 = (const int*)d_in[1];
    const long long* e64 = (const long long*)d_in[1];
    const float*     w1l = (const float*)d_in[2];
    const float*     b1l = (const float*)d_in[3];
    const float*     w1r = (const float*)d_in[4];
    const float*     w2l = (const float*)d_in[5];
    const float*     b2l = (const float*)d_in[6];
    const float*     w2r = (const float*)d_in[7];
    float* out0 = (float*)d_out;       // out [N,1]
    float* outh = out0 + NN;           // h   [N,128]

    detect_kernel<<<1, 32>>>(e32);
    zero_cnt_kernel<<<NB, 256>>>();
    hist_kernel<<<(NE + 255) / 256, 256>>>(e32, e64);
    block_sum_kernel<<<NB, 256>>>();
    scan_partial_kernel<<<1, 512>>>();
    block_scan_kernel<<<NB, 256>>>();
    scatter_kernel<<<(NE + 255) / 256, 256>>>(e32, e64);
    prep_bfrag_kernel<<<(16 * 16 * 2 * 32 + 255) / 256, 256>>>(w1l, w1r);
    agg_kernel<<<(NN * 32 + 255) / 256, 256>>>(x);
    sage1_mma_kernel<<<(NN + BMT - 1) / BMT, 256>>>(x, b1l, outh);
    proj_kernel<<<(NN * 32 + 255) / 256, 256>>>(outh, w2l, b2l, w2r);
    final_kernel<<<(NN + 255) / 256, 256>>>(out0);
}

// round 7
// speedup vs baseline: 1.3570x; 1.0160x over previous
#include <cuda_runtime.h>
#include <cuda_bf16.h>
#include <math.h>
#include <stdint.h>

#define NN 100000
#define NE 1600000
#define DD 128
#define NB 391            // ceil(NN/256)
#define BMT 128           // GEMM M tile per CTA

// Scratch (device globals — no allocation allowed)
__device__ float g_agg[(size_t)NN * DD];
__device__ float g_rcp[NN];
__device__ float g_sl[NN];
__device__ float g_pre[NN];
__device__ uint32_t g_bfh[16 * 16 * 2 * 32];   // B hi frags, [ks][ntg][reg][lane]
__device__ uint32_t g_bfl[16 * 16 * 2 * 32];   // B lo frags
__device__ int   g_cnt[NN];
__device__ int   g_off[NN];
__device__ int   g_cur[NN];
__device__ int   g_esrc[NE];
__device__ int   g_partial[512];
__device__ int   g_pinc[512];
__device__ int   g_is64;

// ---- bf16 helpers -----------------------------------------------------------
__device__ __forceinline__ uint32_t bfpack(float a, float b) {
    __nv_bfloat162 t = __floats2bfloat162_rn(a, b);   // .x = a (low 16 bits)
    return *reinterpret_cast<uint32_t*>(&t);
}
__device__ __forceinline__ float bfres(float v) {
    return v - __bfloat162float(__float2bfloat16_rn(v));
}
#define MMA_BF16(d, a0, a1, a2, a3, b0, b1)                                    \
    asm volatile(                                                              \
        "mma.sync.aligned.m16n8k16.row.col.f32.bf16.bf16.f32 "                 \
        "{%0,%1,%2,%3}, {%4,%5,%6,%7}, {%8,%9}, {%0,%1,%2,%3};"                \
        : "+f"(d[0]), "+f"(d[1]), "+f"(d[2]), "+f"(d[3])                       \
        : "r"(a0), "r"(a1), "r"(a2), "r"(a3), "r"(b0), "r"(b1))

// ---------------------------------------------------------------------------
// Detect edge_index dtype (int32 vs int64).
__global__ void detect_kernel(const int* __restrict__ e) {
    if (threadIdx.x == 0) {
        int z = 0;
#pragma unroll
        for (int i = 1; i < 32; i += 2) z |= e[i];
        g_is64 = (z == 0) ? 1 : 0;
    }
}

__global__ void zero_cnt_kernel() {
    int i = blockIdx.x * 256 + threadIdx.x;
    if (i < NN) g_cnt[i] = 0;
}

__global__ void hist_kernel(const int* __restrict__ e32,
                            const long long* __restrict__ e64) {
    unsigned e = blockIdx.x * 256u + threadIdx.x;
    if (e >= NE) return;
    int dst = g_is64 ? (int)__ldg(&e64[NE + e]) : __ldg(&e32[NE + e]);
    atomicAdd(&g_cnt[dst], 1);
}

__global__ void block_sum_kernel() {
    __shared__ int s[256];
    int b = blockIdx.x, t = threadIdx.x;
    int i = b * 256 + t;
    s[t] = (i < NN) ? g_cnt[i] : 0;
    __syncthreads();
#pragma unroll
    for (int off = 128; off > 0; off >>= 1) {
        if (t < off) s[t] += s[t + off];
        __syncthreads();
    }
    if (t == 0) g_partial[b] = s[0];
}

__global__ void scan_partial_kernel() {
    __shared__ int s[512];
    int t = threadIdx.x;
    s[t] = (t < NB) ? g_partial[t] : 0;
    __syncthreads();
#pragma unroll
    for (int off = 1; off < 512; off <<= 1) {
        int v = (t >= off) ? s[t - off] : 0;
        __syncthreads();
        s[t] += v;
        __syncthreads();
    }
    if (t < NB) g_pinc[t] = s[t];
}

__global__ void block_scan_kernel() {
    __shared__ int s[256];
    int b = blockIdx.x, t = threadIdx.x;
    int i = b * 256 + t;
    int c = (i < NN) ? g_cnt[i] : 0;
    s[t] = c;
    __syncthreads();
#pragma unroll
    for (int off = 1; off < 256; off <<= 1) {
        int v = (t >= off) ? s[t - off] : 0;
        __syncthreads();
        s[t] += v;
        __syncthreads();
    }
    if (i < NN) {
        int base = (b > 0) ? g_pinc[b - 1] : 0;
        int excl = base + s[t] - c;
        g_off[i] = excl;
        g_cur[i] = excl;
        g_rcp[i] = 1.f / fmaxf((float)c, 1.f);
    }
}

__global__ void scatter_kernel(const int* __restrict__ e32,
                               const long long* __restrict__ e64) {
    unsigned e = blockIdx.x * 256u + threadIdx.x;
    if (e >= NE) return;
    int src, dst;
    if (g_is64) {
        src = (int)__ldg(&e64[e]);
        dst = (int)__ldg(&e64[NE + e]);
    } else {
        src = __ldg(&e32[e]);
        dst = __ldg(&e32[NE + e]);
    }
    int pos = atomicAdd(&g_cur[dst], 1);
    g_esrc[pos] = src;
}

// B prep: pack concat(w1l,w1r) into per-thread mma fragment order, bf16 hi/lo.
// Fragment F(ks, ntg, r, lane): elements B[k][n], k = ks*16 + r*8 + (lane&3)*2
// (+1), n = ntg*8 + (lane>>2), where B[k][n] = k<128 ? w1l[n][k] : w1r[n][k-128].
__global__ void prep_bfrag_kernel(const float* __restrict__ w1l,
                                  const float* __restrict__ w1r) {
    int idx = blockIdx.x * 256 + threadIdx.x;      // 0 .. 16383
    if (idx >= 16 * 16 * 2 * 32) return;
    int lane = idx & 31;
    int r    = (idx >> 5) & 1;
    int ntg  = (idx >> 6) & 15;
    int ks   = idx >> 10;
    int k    = ks * 16 + r * 8 + (lane & 3) * 2;
    int n    = ntg * 8 + (lane >> 2);
    float v0 = (k < DD)     ? w1l[n * DD + k]       : w1r[n * DD + k - DD];
    float v1 = (k + 1 < DD) ? w1l[n * DD + k + 1]   : w1r[n * DD + k + 1 - DD];
    g_bfh[idx] = bfpack(v0, v1);
    g_bfl[idx] = bfpack(bfres(v0), bfres(v1));
}

// ---------------------------------------------------------------------------
// Gather-style mean aggregation: one warp per node, neighbors from CSR.
__global__ void __launch_bounds__(256) agg_kernel(const float* __restrict__ x) {
    unsigned tid  = blockIdx.x * 256u + threadIdx.x;
    unsigned row  = tid >> 5;
    if (row >= NN) return;
    unsigned lane = tid & 31;
    int beg = g_off[row];
    int end = beg + g_cnt[row];
    float4 a0 = make_float4(0.f, 0.f, 0.f, 0.f);
    float4 a1 = make_float4(0.f, 0.f, 0.f, 0.f);
    int e = beg;
    for (; e + 1 < end; e += 2) {
        int s0 = __ldg(&g_esrc[e]);
        int s1 = __ldg(&g_esrc[e + 1]);
        float4 v0 = __ldg((const float4*)(x + (size_t)s0 * DD) + lane);
        float4 v1 = __ldg((const float4*)(x + (size_t)s1 * DD) + lane);
        a0.x += v0.x; a0.y += v0.y; a0.z += v0.z; a0.w += v0.w;
        a1.x += v1.x; a1.y += v1.y; a1.z += v1.z; a1.w += v1.w;
    }
    if (e < end) {
        int s0 = __ldg(&g_esrc[e]);
        float4 v0 = __ldg((const float4*)(x + (size_t)s0 * DD) + lane);
        a0.x += v0.x; a0.y += v0.y; a0.z += v0.z; a0.w += v0.w;
    }
    float r = g_rcp[row];
    float4 m = make_float4((a0.x + a1.x) * r, (a0.y + a1.y) * r,
                           (a0.z + a1.z) * r, (a0.w + a1.w) * r);
    *((float4*)(g_agg + (size_t)row * DD) + lane) = m;
}

// ---------------------------------------------------------------------------
// Layer-1 GEMM on tensor cores via mma.sync bf16 with 3-term hi/lo split.
// CTA: 128 rows x 128 cols. 8 warps in 4(M) x 2(N); warp = 32 rows x 64 cols.
// A fragments loaded directly from global fp32 (float2 per reg pair) and split
// to bf16 hi/lo in registers; B fragments pre-packed in g_bfh/g_bfl.
__global__ void __launch_bounds__(256) sage1_mma_kernel(
    const float* __restrict__ x, const float* __restrict__ b1l,
    float* __restrict__ outh) {
    const int tid  = threadIdx.x;
    const int w    = tid >> 5;
    const int lane = tid & 31;
    const int gid  = lane >> 2;
    const int tig  = lane & 3;
    const int m0   = blockIdx.x * BMT;

    const int mrow   = m0 + (w & 3) * 32;
    const int ncol   = (w >> 2) * 64;
    const int ntbase = (w >> 2) * 8;

    float acc[2][8][4];
#pragma unroll
    for (int mt = 0; mt < 2; mt++)
#pragma unroll
        for (int nt = 0; nt < 8; nt++)
#pragma unroll
            for (int q = 0; q < 4; q++) acc[mt][nt][q] = 0.f;

#pragma unroll 1
    for (int ks = 0; ks < 16; ks++) {
        // k<128 comes from g_agg (mean), k>=128 from x; ks<8 <=> k<128.
        const float* base = (ks < 8) ? (const float*)g_agg : (x - DD);
        const int kk = ks * 16 + tig * 2;

        uint32_t ah[2][4], al[2][4];
#pragma unroll
        for (int mt = 0; mt < 2; mt++) {
            int ra = mrow + mt * 16 + gid;
            int rb = ra + 8;
            bool va = ra < NN, vb = rb < NN;
            float2 z = make_float2(0.f, 0.f);
            float2 p0 = va ? *(const float2*)(base + (size_t)ra * DD + kk)     : z;
            float2 p1 = vb ? *(const float2*)(base + (size_t)rb * DD + kk)     : z;
            float2 p2 = va ? *(const float2*)(base + (size_t)ra * DD + kk + 8) : z;
            float2 p3 = vb ? *(const float2*)(base + (size_t)rb * DD + kk + 8) : z;
            ah[mt][0] = bfpack(p0.x, p0.y);
            ah[mt][1] = bfpack(p1.x, p1.y);
            ah[mt][2] = bfpack(p2.x, p2.y);
            ah[mt][3] = bfpack(p3.x, p3.y);
            al[mt][0] = bfpack(bfres(p0.x), bfres(p0.y));
            al[mt][1] = bfpack(bfres(p1.x), bfres(p1.y));
            al[mt][2] = bfpack(bfres(p2.x), bfres(p2.y));
            al[mt][3] = bfpack(bfres(p3.x), bfres(p3.y));
        }

#pragma unroll
        for (int nt = 0; nt < 8; nt++) {
            int fi = ((ks * 16 + ntbase + nt) * 2) * 32 + lane;
            uint32_t bh0 = __ldg(&g_bfh[fi]);
            uint32_t bh1 = __ldg(&g_bfh[fi + 32]);
            uint32_t bl0 = __ldg(&g_bfl[fi]);
            uint32_t bl1 = __ldg(&g_bfl[fi + 32]);
#pragma unroll
            for (int mt = 0; mt < 2; mt++) {
                MMA_BF16(acc[mt][nt], ah[mt][0], ah[mt][1], ah[mt][2], ah[mt][3],
                         bh0, bh1);
                MMA_BF16(acc[mt][nt], al[mt][0], al[mt][1], al[mt][2], al[mt][3],
                         bh0, bh1);
                MMA_BF16(acc[mt][nt], ah[mt][0], ah[mt][1], ah[mt][2], ah[mt][3],
                         bl0, bl1);
            }
        }
    }

    // Epilogue: + bias, store h (pre-relu). D frag: d0,d1 -> (gid, 2tig/+1);
    // d2,d3 -> (gid+8, 2tig/+1).
#pragma unroll
    for (int mt = 0; mt < 2; mt++) {
        int ra = mrow + mt * 16 + gid;
        int rb = ra + 8;
#pragma unroll
        for (int nt = 0; nt < 8; nt++) {
            int col = ncol + nt * 8 + tig * 2;
            float2 bias = *(const float2*)(b1l + col);
            if (ra < NN)
                *(float2*)(outh + (size_t)ra * DD + col) =
                    make_float2(acc[mt][nt][0] + bias.x, acc[mt][nt][1] + bias.y);
            if (rb < NN)
                *(float2*)(outh + (size_t)rb * DD + col) =
                    make_float2(acc[mt][nt][2] + bias.x, acc[mt][nt][3] + bias.y);
        }
    }
}

// ---------------------------------------------------------------------------
// Layer-2 projection: one warp per row.
__global__ void __launch_bounds__(256) proj_kernel(
    const float* __restrict__ outh,
    const float* __restrict__ w2l, const float* __restrict__ b2l,
    const float* __restrict__ w2r) {
    unsigned tid  = blockIdx.x * 256u + threadIdx.x;
    unsigned row  = tid >> 5;
    if (row >= NN) return;
    unsigned lane = tid & 31;
    float4 h  = __ldg((const float4*)(outh + (size_t)row * DD) + lane);
    float4 wl = __ldg((const float4*)w2l + lane);
    float4 wr = __ldg((const float4*)w2r + lane);
    float r0 = fmaxf(h.x, 0.f), r1 = fmaxf(h.y, 0.f);
    float r2 = fmaxf(h.z, 0.f), r3 = fmaxf(h.w, 0.f);
    float sl = r0 * wl.x + r1 * wl.y + r2 * wl.z + r3 * wl.w;
    float sr = r0 * wr.x + r1 * wr.y + r2 * wr.z + r3 * wr.w;
#pragma unroll
    for (int off = 16; off > 0; off >>= 1) {
        sl += __shfl_xor_sync(0xffffffffu, sl, off);
        sr += __shfl_xor_sync(0xffffffffu, sr, off);
    }
    if (lane == 0) { g_sl[row] = sl; g_pre[row] = sr + __ldg(b2l); }
}

// Layer-2 aggregation (CSR gather) + sigmoid, fused.
__global__ void final_kernel(float* __restrict__ out0) {
    int i = blockIdx.x * 256 + threadIdx.x;
    if (i >= NN) return;
    int beg = g_off[i];
    int end = beg + g_cnt[i];
    float t = 0.f;
    for (int e = beg; e < end; e++) t += __ldg(&g_sl[__ldg(&g_esrc[e])]);
    float v = t * g_rcp[i] + g_pre[i];
    out0[i] = 1.f / (1.f + expf(-v));
}

// ---------------------------------------------------------------------------
extern "C" void kernel_launch(void* const* d_in, const int* in_sizes, int n_in,
                              void* d_out, int out_size) {
    const float*     x   = (const float*)d_in[0];
    const int*       e32 = (const int*)d_in[1];
    const long long* e64 = (const long long*)d_in[1];
    const float*     w1l = (const float*)d_in[2];
    const float*     b1l = (const float*)d_in[3];
    const float*     w1r = (const float*)d_in[4];
    const float*     w2l = (const float*)d_in[5];
    const float*     b2l = (const float*)d_in[6];
    const float*     w2r = (const float*)d_in[7];
    float* out0 = (float*)d_out;       // out [N,1]
    float* outh = out0 + NN;           // h   [N,128]

    detect_kernel<<<1, 32>>>(e32);
    zero_cnt_kernel<<<NB, 256>>>();
    hist_kernel<<<(NE + 255) / 256, 256>>>(e32, e64);
    block_sum_kernel<<<NB, 256>>>();
    scan_partial_kernel<<<1, 512>>>();
    block_scan_kernel<<<NB, 256>>>();
    scatter_kernel<<<(NE + 255) / 256, 256>>>(e32, e64);
    prep_bfrag_kernel<<<(16 * 16 * 2 * 32 + 255) / 256, 256>>>(w1l, w1r);
    agg_kernel<<<(NN * 32 + 255) / 256, 256>>>(x);
    sage1_mma_kernel<<<(NN + BMT - 1) / BMT, 256>>>(x, b1l, outh);
    proj_kernel<<<(NN * 32 + 255) / 256, 256>>>(outh, w2l, b2l, w2r);
    final_kernel<<<(NN + 255) / 256, 256>>>(out0);
}